// round 1
// baseline (speedup 1.0000x reference)
#include <cuda_runtime.h>

// Problem constants
#define NT      2048        // B*L tokens
#define DIM     512
#define VOCAB   32000
#define SEG     8000        // VOCAB / 4
#define RANKS   4
#define TM      16          // tokens per CTA
#define TN      64          // vocab rows per tile
#define NTILES  (SEG / TN)  // 125
#define THREADS 256
#define QPITCH  513         // padded row pitch (floats) for q/e smem tiles

// Scratch (allocation-free rule: device globals)
__device__ int g_cnt[RANKS];
__device__ int g_list[RANKS][NT];

__global__ void k_zero() {
    if (threadIdx.x < RANKS) g_cnt[threadIdx.x] = 0;
}

__global__ void k_build(const int* __restrict__ xr) {
    int i = blockIdx.x * blockDim.x + threadIdx.x;
    if (i < NT) {
        int r = xr[i];
        int p = atomicAdd(&g_cnt[r], 1);
        g_list[r][p] = i;
    }
}

// Dynamic smem layout (floats):
//   q_s  : TM * 513            = 8208
//   e_s  : TN * 513            = 32832
//   Sp   : 4 * TM * TN         = 4096   (per-D-slice score partials)
//   P    : TM * 65             = 1040   (exp(scores), padded)
// total 46176 floats = 184704 bytes
#define SMEM_FLOATS (TM*QPITCH + TN*QPITCH + 4*TM*TN + TM*65)

__global__ void __launch_bounds__(THREADS, 1)
k_main(const float* __restrict__ qg, const float* __restrict__ emb,
       float* __restrict__ out)
{
    const int r   = blockIdx.y;
    const int cnt = g_cnt[r];
    const int t0g = blockIdx.x * TM;
    if (t0g >= cnt) return;
    const int ntok = min(TM, cnt - t0g);

    extern __shared__ float sm[];
    float* q_s = sm;                       // [TM][513]
    float* e_s = q_s + TM * QPITCH;        // [TN][513]
    float* Sp  = e_s + TN * QPITCH;        // [4][TM][TN]
    float* P   = Sp  + 4 * TM * TN;        // [TM][65]

    __shared__ int   toks[TM];
    __shared__ float lrow[TM];

    const int tid = threadIdx.x;

    if (tid < TM) {
        toks[tid] = (t0g + tid < cnt) ? g_list[r][t0g + tid] : g_list[r][t0g];
        lrow[tid] = 0.0f;
    }
    __syncthreads();

    // Load q tile (pre-scaled by 1/sqrt(512))
    const float invT = 0.04419417382415922f;
    #pragma unroll
    for (int i = 0; i < (TM * DIM) / THREADS; ++i) {   // 32 iters
        int idx = tid + i * THREADS;
        int t = idx >> 9, d = idx & 511;
        q_s[t * QPITCH + d] = qg[(size_t)toks[t] * DIM + d] * invT;
    }

    // Phase-1 mapping: slice (D quarter) x (4 token rows x 4 vocab cols)
    const int slice = tid >> 6;
    const int pos   = tid & 63;
    const int p1_t0 = (pos & 3) * 4;       // token base  {0,4,8,12}
    const int p1_v0 = (pos >> 2) * 4;      // vocab base  {0..60}
    const int dbase = slice * 128;

    // Phase-2 mapping: 4 token-groups x 64 dim-groups (8 dims each)
    const int tg    = tid & 3;
    const int dg    = tid >> 2;
    const int p2_t0 = tg * 4;
    const int p2_d0 = dg * 8;

    float ctx[4][8];
    #pragma unroll
    for (int i = 0; i < 4; ++i)
        #pragma unroll
        for (int k = 0; k < 8; ++k) ctx[i][k] = 0.0f;

    const size_t segbase = (size_t)r * SEG;

    for (int tile = 0; tile < NTILES; ++tile) {
        __syncthreads();   // protect e_s / q_s before overwrite / first use

        // ---- load emb tile [TN][512] into padded smem, coalesced ----
        const float* esrc = emb + (segbase + (size_t)tile * TN) * DIM;
        #pragma unroll
        for (int i = 0; i < (TN * DIM) / THREADS; ++i) {   // 128 iters
            int idx = tid + i * THREADS;
            int v = idx >> 9, d = idx & 511;
            e_s[v * QPITCH + d] = esrc[idx];
        }
        __syncthreads();

        // ---- phase 1: S[t][v] partials over this thread's D slice ----
        {
            float acc[4][4];
            #pragma unroll
            for (int i = 0; i < 4; ++i)
                #pragma unroll
                for (int j = 0; j < 4; ++j) acc[i][j] = 0.0f;

            const float* qp = q_s + p1_t0 * QPITCH + dbase;
            const float* ep = e_s + p1_v0 * QPITCH + dbase;

            #pragma unroll 4
            for (int d = 0; d < 128; ++d) {
                float qv[4], ev[4];
                #pragma unroll
                for (int i = 0; i < 4; ++i) qv[i] = qp[i * QPITCH + d];
                #pragma unroll
                for (int j = 0; j < 4; ++j) ev[j] = ep[j * QPITCH + d];
                #pragma unroll
                for (int i = 0; i < 4; ++i)
                    #pragma unroll
                    for (int j = 0; j < 4; ++j)
                        acc[i][j] += qv[i] * ev[j];
            }

            #pragma unroll
            for (int i = 0; i < 4; ++i)
                #pragma unroll
                for (int j = 0; j < 4; ++j)
                    Sp[(slice * TM + p1_t0 + i) * TN + p1_v0 + j] = acc[i][j];
        }
        __syncthreads();

        // ---- reduce slices + exp (scores are tiny; no max-subtraction needed) ----
        #pragma unroll
        for (int k = 0; k < 4; ++k) {
            int idx = tid + k * THREADS;          // 0..1023
            int t = idx >> 6, v = idx & 63;
            float s = Sp[t * TN + v]
                    + Sp[(TM + t) * TN + v]
                    + Sp[(2 * TM + t) * TN + v]
                    + Sp[(3 * TM + t) * TN + v];
            P[t * 65 + v] = __expf(s);
        }
        __syncthreads();

        // ---- row-sum of P (fixed order => deterministic) ----
        if (tid < TM) {
            float s = 0.0f;
            #pragma unroll 8
            for (int v = 0; v < TN; ++v) s += P[tid * 65 + v];
            lrow[tid] += s;
        }

        // ---- phase 2: ctx[t][d] += P[t][v] * e[v][d] ----
        #pragma unroll 2
        for (int v = 0; v < TN; ++v) {
            float pv[4];
            #pragma unroll
            for (int i = 0; i < 4; ++i) pv[i] = P[(p2_t0 + i) * 65 + v];
            const float* er = e_s + v * QPITCH + p2_d0;
            #pragma unroll
            for (int k = 0; k < 8; ++k) {
                float e = er[k];
                #pragma unroll
                for (int i = 0; i < 4; ++i) ctx[i][k] += pv[i] * e;
            }
        }
    }

    __syncthreads();   // lrow final

    // ---- epilogue: out = ctx / l + q ----
    #pragma unroll
    for (int i = 0; i < 4; ++i) {
        int trow = p2_t0 + i;
        if (trow < ntok) {
            int tok = toks[trow];
            float linv = 1.0f / lrow[trow];
            const float* qsrc = qg  + (size_t)tok * DIM + p2_d0;
            float*       od   = out + (size_t)tok * DIM + p2_d0;
            #pragma unroll
            for (int k = 0; k < 8; ++k)
                od[k] = ctx[i][k] * linv + qsrc[k];
        }
    }
}

extern "C" void kernel_launch(void* const* d_in, const int* in_sizes, int n_in,
                              void* d_out, int out_size)
{
    const float* q   = (const float*)d_in[0];
    const int*   xr  = (const int*)  d_in[1];
    const float* emb = (const float*)d_in[2];
    float*       out = (float*)d_out;

    const size_t smem_bytes = SMEM_FLOATS * sizeof(float);   // 184704
    cudaFuncSetAttribute((const void*)k_main,
                         cudaFuncAttributeMaxDynamicSharedMemorySize,
                         (int)smem_bytes);

    k_zero<<<1, 32>>>();
    k_build<<<NT / 256, 256>>>(xr);

    dim3 grid(NT / TM, RANKS);   // worst case: all tokens in one rank
    k_main<<<grid, THREADS, smem_bytes>>>(q, emb, out);
}

// round 3
// speedup vs baseline: 4.5616x; 4.5616x over previous
#include <cuda_runtime.h>
#include <cuda_bf16.h>
#include <cstdint>

#define NT    2048
#define DIM   512
#define SEG   8000
#define SEGP  8192
#define RANKS 4

// ---------------- scratch (device globals; no allocs allowed) ----------------
__device__ int g_cnt[RANKS];
__device__ int g_list[RANKS][NT];
__device__ __align__(128) __nv_bfloat16 g_qh[NT * DIM];                     // q*invT bf16
__device__ __align__(128) __nv_bfloat16 g_embh[(size_t)RANKS * SEGP * DIM]; // [r][v][d], padded
__device__ __align__(128) __nv_bfloat16 g_P[(size_t)NT * SEGP];             // exp(scores)
__device__ float g_lpart[NT][4];                                            // row-sum partials

// ---------------- helpers ----------------
__device__ __forceinline__ uint32_t smem_u32(const void* p) {
    uint32_t a;
    asm("{ .reg .u64 t; cvta.to.shared.u64 t, %1; cvt.u32.u64 %0, t; }" : "=r"(a) : "l"(p));
    return a;
}
__device__ __forceinline__ void cpa16(uint32_t d, const void* s) {
    asm volatile("cp.async.cg.shared.global [%0], [%1], 16;" :: "r"(d), "l"(s));
}
#define CPA_COMMIT() asm volatile("cp.async.commit_group;" ::: "memory")
#define CPA_WAIT(n)  asm volatile("cp.async.wait_group %0;" :: "n"(n) : "memory")

__device__ __forceinline__ void ldsm4(uint32_t f[4], uint32_t a) {
    asm volatile("ldmatrix.sync.aligned.m8n8.x4.shared.b16 {%0,%1,%2,%3}, [%4];"
        : "=r"(f[0]), "=r"(f[1]), "=r"(f[2]), "=r"(f[3]) : "r"(a));
}
__device__ __forceinline__ void ldsm2(uint32_t f[2], uint32_t a) {
    asm volatile("ldmatrix.sync.aligned.m8n8.x2.shared.b16 {%0,%1}, [%2];"
        : "=r"(f[0]), "=r"(f[1]) : "r"(a));
}
__device__ __forceinline__ void ldsm2t(uint32_t f[2], uint32_t a) {
    asm volatile("ldmatrix.sync.aligned.m8n8.x2.trans.shared.b16 {%0,%1}, [%2];"
        : "=r"(f[0]), "=r"(f[1]) : "r"(a));
}
__device__ __forceinline__ void mma16816(float c[4], const uint32_t a[4], const uint32_t b[2]) {
    asm volatile("mma.sync.aligned.m16n8k16.row.col.f32.bf16.bf16.f32 "
        "{%0,%1,%2,%3}, {%4,%5,%6,%7}, {%8,%9}, {%0,%1,%2,%3};"
        : "+f"(c[0]), "+f"(c[1]), "+f"(c[2]), "+f"(c[3])
        : "r"(a[0]), "r"(a[1]), "r"(a[2]), "r"(a[3]), "r"(b[0]), "r"(b[1]));
}

// ---------------- small kernels ----------------
__global__ void k_zero() { if (threadIdx.x < RANKS) g_cnt[threadIdx.x] = 0; }

__global__ void k_build(const int* __restrict__ xr) {
    int i = blockIdx.x * blockDim.x + threadIdx.x;
    if (i < NT) {
        int r = xr[i];
        int p = atomicAdd(&g_cnt[r], 1);
        g_list[r][p] = i;
    }
}

__global__ void k_prep_q(const float* __restrict__ q) {
    int i = blockIdx.x * 256 + threadIdx.x;              // 131072 groups of 8
    const float inv = 0.04419417382415922f;              // 1/sqrt(512)
    float4 a = *reinterpret_cast<const float4*>(q + (size_t)i * 8);
    float4 b = *reinterpret_cast<const float4*>(q + (size_t)i * 8 + 4);
    __nv_bfloat16 h[8];
    h[0] = __float2bfloat16(a.x * inv); h[1] = __float2bfloat16(a.y * inv);
    h[2] = __float2bfloat16(a.z * inv); h[3] = __float2bfloat16(a.w * inv);
    h[4] = __float2bfloat16(b.x * inv); h[5] = __float2bfloat16(b.y * inv);
    h[6] = __float2bfloat16(b.z * inv); h[7] = __float2bfloat16(b.w * inv);
    *reinterpret_cast<uint4*>(g_qh + (size_t)i * 8) = *reinterpret_cast<uint4*>(h);
}

__global__ void k_prep_emb(const float* __restrict__ emb) {
    int i = blockIdx.x * 256 + threadIdx.x;              // 2,097,152 groups of 8
    int d8 = i & 63;
    int vv = i >> 6;                                     // r*8192+v
    int r = vv >> 13, v = vv & 8191;
    __nv_bfloat16 h[8];
    if (v < SEG) {
        const float* s = emb + ((size_t)r * SEG + v) * DIM + d8 * 8;
        float4 a = *reinterpret_cast<const float4*>(s);
        float4 b = *reinterpret_cast<const float4*>(s + 4);
        h[0] = __float2bfloat16(a.x); h[1] = __float2bfloat16(a.y);
        h[2] = __float2bfloat16(a.z); h[3] = __float2bfloat16(a.w);
        h[4] = __float2bfloat16(b.x); h[5] = __float2bfloat16(b.y);
        h[6] = __float2bfloat16(b.z); h[7] = __float2bfloat16(b.w);
    } else {
        #pragma unroll
        for (int m = 0; m < 8; ++m) h[m] = __float2bfloat16(0.f);
    }
    *reinterpret_cast<uint4*>(g_embh + (size_t)vv * DIM + d8 * 8) = *reinterpret_cast<uint4*>(h);
}

// ---------------- pass 1: P = exp(Q.E^T), row-sum partials ----------------
// grid (16 token tiles, 4 ranks, 4 vsplits of 2048 rows); 256 thr; smem Q 128K + E 64K
__global__ void __launch_bounds__(256, 1)
k_scores() {
    int r = blockIdx.y;
    int cnt = g_cnt[r];
    int t0 = blockIdx.x * 128;
    if (t0 >= cnt) return;
    int vs = blockIdx.z;

    extern __shared__ char sm[];
    __shared__ int   toks[128];
    __shared__ float rs[2][128];

    const int tid = threadIdx.x, lane = tid & 31, wid = tid >> 5;
    const int mg = wid >> 1, ng = wid & 1;

    for (int i = tid; i < 128; i += 256) toks[i] = g_list[r][min(t0 + i, cnt - 1)];
    rs[tid >> 7][tid & 127] = 0.f;
    __syncthreads();

    const uint32_t qs = smem_u32(sm), es = qs + 131072;

    // Q tile: 128 rows x 64 chunks(16B), swizzled c^(row&7)
    for (int i = tid; i < 8192; i += 256) {
        int rr = i >> 6, c = i & 63;
        cpa16(qs + rr * 1024 + ((c ^ (rr & 7)) << 4),
              g_qh + (size_t)toks[rr] * DIM + c * 8);
    }
    CPA_COMMIT();

    // ldmatrix lane-constant pieces
    const int la7 = lane & 7;
    const int aRow0 = mg * 32 + la7 + ((lane >> 3) & 1) * 8;   // +mi*16
    const int aChB  = lane >> 4;                               // chunk add for A
    const int bRow0 = ng * 32 + la7;                           // +ni*8
    const int bChB  = (lane >> 3) & 1;
    const int epiV  = (lane & 3) * 2;

    const size_t vsbase = (size_t)vs * 2048;

    for (int tile = 0; tile < 32; ++tile) {
        __syncthreads();   // previous mma done reading Es
        // E tile: 64 rows x 64 chunks
        size_t v0 = vsbase + (size_t)tile * 64;
        const __nv_bfloat16* esrc = g_embh + ((size_t)r * SEGP + v0) * DIM;
        for (int i = tid; i < 4096; i += 256) {
            int rr = i >> 6, c = i & 63;
            cpa16(es + rr * 1024 + ((c ^ (rr & 7)) << 4),
                  esrc + (size_t)rr * DIM + c * 8);
        }
        CPA_COMMIT();
        CPA_WAIT(0);
        __syncthreads();

        float c[2][4][4];
        #pragma unroll
        for (int mi = 0; mi < 2; ++mi)
            #pragma unroll
            for (int ni = 0; ni < 4; ++ni)
                #pragma unroll
                for (int j = 0; j < 4; ++j) c[mi][ni][j] = 0.f;

        #pragma unroll 4
        for (int ks = 0; ks < 32; ++ks) {
            uint32_t a0[4], a1[4], b[2];
            uint32_t aswz = (uint32_t)(((ks * 2 + aChB) ^ la7) << 4);
            ldsm4(a0, qs + aRow0 * 1024 + aswz);
            ldsm4(a1, qs + (aRow0 + 16) * 1024 + aswz);
            uint32_t bswz = (uint32_t)(((ks * 2 + bChB) ^ la7) << 4);
            #pragma unroll
            for (int ni = 0; ni < 4; ++ni) {
                ldsm2(b, es + (bRow0 + ni * 8) * 1024 + bswz);
                mma16816(c[0][ni], a0, b);
                mma16816(c[1][ni], a1, b);
            }
        }

        // epilogue: exp, P->global (bf16), row sums
        int vb = (int)v0 + ng * 32;
        #pragma unroll
        for (int mi = 0; mi < 2; ++mi) {
            int rowlo = mg * 32 + mi * 16 + (lane >> 2);
            int rowhi = rowlo + 8;
            int toklo = toks[rowlo], tokhi = toks[rowhi];
            float slo = 0.f, shi = 0.f;
            #pragma unroll
            for (int ni = 0; ni < 4; ++ni) {
                int v = vb + ni * 8 + epiV;
                float p0 = (v     < SEG) ? __expf(c[mi][ni][0]) : 0.f;
                float p1 = (v + 1 < SEG) ? __expf(c[mi][ni][1]) : 0.f;
                float p2 = (v     < SEG) ? __expf(c[mi][ni][2]) : 0.f;
                float p3 = (v + 1 < SEG) ? __expf(c[mi][ni][3]) : 0.f;
                slo += p0 + p1; shi += p2 + p3;
                __nv_bfloat162 h0 = __floats2bfloat162_rn(p0, p1);
                __nv_bfloat162 h1 = __floats2bfloat162_rn(p2, p3);
                *reinterpret_cast<uint32_t*>(g_P + (size_t)toklo * SEGP + v) =
                    *reinterpret_cast<uint32_t*>(&h0);
                *reinterpret_cast<uint32_t*>(g_P + (size_t)tokhi * SEGP + v) =
                    *reinterpret_cast<uint32_t*>(&h1);
            }
            slo += __shfl_xor_sync(0xffffffffu, slo, 1);
            slo += __shfl_xor_sync(0xffffffffu, slo, 2);
            shi += __shfl_xor_sync(0xffffffffu, shi, 1);
            shi += __shfl_xor_sync(0xffffffffu, shi, 2);
            if ((lane & 3) == 0) { rs[ng][rowlo] += slo; rs[ng][rowhi] += shi; }
        }
    }
    __syncthreads();
    for (int i = tid; i < 128; i += 256)
        g_lpart[toks[i]][vs] = rs[0][i] + rs[1][i];
}

// ---------------- pass 2: out = (P.E)/l + q ----------------
__device__ __forceinline__ void k2_load(uint32_t pt, uint32_t et, int buf,
                                        const int* toks, int rank, int ns,
                                        int ch, int tid) {
    size_t kc0 = (size_t)ch * 64;
    uint32_t pd = pt + buf * 16384, ed = et + buf * 16384;
    #pragma unroll
    for (int j = 0; j < 4; ++j) {                        // P: 128 rows x 8 chunks
        int i = tid + j * 256; int rr = i >> 3, cc = i & 7;
        cpa16(pd + rr * 128 + ((cc ^ (rr & 7)) << 4),
              g_P + (size_t)toks[rr] * SEGP + kc0 + cc * 8);
    }
    #pragma unroll
    for (int j = 0; j < 4; ++j) {                        // E: 64 rows x 16 chunks
        int i = tid + j * 256; int rr = i >> 4, cc = i & 15;
        cpa16(ed + rr * 256 + ((cc ^ (rr & 7)) << 4),
              g_embh + ((size_t)rank * SEGP + kc0 + rr) * DIM + (size_t)ns * 128 + cc * 8);
    }
}

// grid (16 token tiles, 4 ranks, 4 d-splits of 128); 256 thr; smem 64KB (2x(16K+16K))
__global__ void __launch_bounds__(256, 1)
k_ctx(const float* __restrict__ qg, float* __restrict__ out) {
    int r = blockIdx.y;
    int cnt = g_cnt[r];
    int t0 = blockIdx.x * 128;
    if (t0 >= cnt) return;
    int ns = blockIdx.z;

    extern __shared__ char sm[];
    __shared__ int   toks[128];
    __shared__ float slinv[128];

    const int tid = threadIdx.x, lane = tid & 31, wid = tid >> 5;
    const int mg = wid >> 1, ng = wid & 1;

    for (int i = tid; i < 128; i += 256) toks[i] = g_list[r][min(t0 + i, cnt - 1)];
    __syncthreads();
    for (int i = tid; i < 128; i += 256) {
        int tok = toks[i];
        slinv[i] = 1.f / (g_lpart[tok][0] + g_lpart[tok][1] +
                          g_lpart[tok][2] + g_lpart[tok][3]);
    }

    const uint32_t pt = smem_u32(sm), et = pt + 32768;

    float c[2][8][4];
    #pragma unroll
    for (int mi = 0; mi < 2; ++mi)
        #pragma unroll
        for (int ni = 0; ni < 8; ++ni)
            #pragma unroll
            for (int j = 0; j < 4; ++j) c[mi][ni][j] = 0.f;

    const int la7 = lane & 7;
    const int aRow0 = mg * 32 + la7 + ((lane >> 3) & 1) * 8;   // +mi*16
    const int aChB  = lane >> 4;
    const int bKr0  = la7 + ((lane >> 3) & 1) * 8;             // +ks*16

    k2_load(pt, et, 0, toks, r, ns, 0, tid);
    CPA_COMMIT();

    for (int ch = 0; ch < 128; ++ch) {
        if (ch < 127) {
            k2_load(pt, et, (ch + 1) & 1, toks, r, ns, ch + 1, tid);
            CPA_COMMIT();
            CPA_WAIT(1);
        } else {
            CPA_WAIT(0);
        }
        __syncthreads();

        uint32_t pb = pt + (ch & 1) * 16384;
        uint32_t eb = et + (ch & 1) * 16384;
        #pragma unroll
        for (int ks = 0; ks < 4; ++ks) {
            uint32_t a0[4], a1[4], b[2];
            uint32_t aswz = (uint32_t)(((ks * 2 + aChB) ^ la7) << 4);
            ldsm4(a0, pb + aRow0 * 128 + aswz);
            ldsm4(a1, pb + (aRow0 + 16) * 128 + aswz);
            int krow = ks * 16 + bKr0;
            #pragma unroll
            for (int ni = 0; ni < 8; ++ni) {
                ldsm2t(b, eb + krow * 256 + (((ng * 8 + ni) ^ la7) << 4));
                mma16816(c[0][ni], a0, b);
                mma16816(c[1][ni], a1, b);
            }
        }
        __syncthreads();
    }

    // epilogue: out = ctx*linv + q
    #pragma unroll
    for (int mi = 0; mi < 2; ++mi) {
        int rowlo = mg * 32 + mi * 16 + (lane >> 2);
        int rowhi = rowlo + 8;
        int toklo = toks[rowlo], tokhi = toks[rowhi];
        float ll = slinv[rowlo], lh = slinv[rowhi];
        #pragma unroll
        for (int ni = 0; ni < 8; ++ni) {
            int col = ns * 128 + ng * 64 + ni * 8 + (lane & 3) * 2;
            size_t olo = (size_t)toklo * DIM + col;
            size_t ohi = (size_t)tokhi * DIM + col;
            float2 qa = *reinterpret_cast<const float2*>(qg + olo);
            float2 qb = *reinterpret_cast<const float2*>(qg + ohi);
            float2 wa, wb;
            wa.x = c[mi][ni][0] * ll + qa.x; wa.y = c[mi][ni][1] * ll + qa.y;
            wb.x = c[mi][ni][2] * lh + qb.x; wb.y = c[mi][ni][3] * lh + qb.y;
            *reinterpret_cast<float2*>(out + olo) = wa;
            *reinterpret_cast<float2*>(out + ohi) = wb;
        }
    }
}

// ---------------- launch ----------------
extern "C" void kernel_launch(void* const* d_in, const int* in_sizes, int n_in,
                              void* d_out, int out_size) {
    const float* q   = (const float*)d_in[0];
    const int*   xr  = (const int*)  d_in[1];
    const float* emb = (const float*)d_in[2];
    float*       out = (float*)d_out;

    cudaFuncSetAttribute((const void*)k_scores,
                         cudaFuncAttributeMaxDynamicSharedMemorySize, 196608);
    cudaFuncSetAttribute((const void*)k_ctx,
                         cudaFuncAttributeMaxDynamicSharedMemorySize, 65536);

    k_zero<<<1, 32>>>();
    k_build<<<NT / 256, 256>>>(xr);
    k_prep_q<<<512, 256>>>(q);
    k_prep_emb<<<8192, 256>>>(emb);

    dim3 g(16, 4, 4);
    k_scores<<<g, 256, 196608>>>();
    k_ctx<<<g, 256, 65536>>>(q, out);
}

// round 4
// speedup vs baseline: 4.7895x; 1.0500x over previous
#include <cuda_runtime.h>
#include <cuda_bf16.h>
#include <cstdint>

#define NT    2048
#define DIM   512
#define SEG   8000
#define SEGP  8192
#define RANKS 4

// ---------------- scratch (device globals; no allocs allowed) ----------------
__device__ int g_cnt[RANKS];
__device__ int g_list[RANKS][NT];
__device__ __align__(128) __nv_bfloat16 g_qh[NT * DIM];                     // q*invT bf16
__device__ __align__(128) __nv_bfloat16 g_embh[(size_t)RANKS * SEGP * DIM]; // [r][v][d], padded
__device__ __align__(128) __nv_bfloat16 g_P[(size_t)NT * SEGP];             // exp(scores)
__device__ float g_lpart[NT][8];                                            // row-sum partials

// ---------------- helpers ----------------
__device__ __forceinline__ uint32_t smem_u32(const void* p) {
    uint32_t a;
    asm("{ .reg .u64 t; cvta.to.shared.u64 t, %1; cvt.u32.u64 %0, t; }" : "=r"(a) : "l"(p));
    return a;
}
__device__ __forceinline__ void cpa16(uint32_t d, const void* s) {
    asm volatile("cp.async.cg.shared.global [%0], [%1], 16;" :: "r"(d), "l"(s));
}
#define CPA_COMMIT() asm volatile("cp.async.commit_group;" ::: "memory")
#define CPA_WAIT(n)  asm volatile("cp.async.wait_group %0;" :: "n"(n) : "memory")

__device__ __forceinline__ void ldsm4(uint32_t f[4], uint32_t a) {
    asm volatile("ldmatrix.sync.aligned.m8n8.x4.shared.b16 {%0,%1,%2,%3}, [%4];"
        : "=r"(f[0]), "=r"(f[1]), "=r"(f[2]), "=r"(f[3]) : "r"(a));
}
__device__ __forceinline__ void ldsm2(uint32_t f[2], uint32_t a) {
    asm volatile("ldmatrix.sync.aligned.m8n8.x2.shared.b16 {%0,%1}, [%2];"
        : "=r"(f[0]), "=r"(f[1]) : "r"(a));
}
__device__ __forceinline__ void ldsm2t(uint32_t f[2], uint32_t a) {
    asm volatile("ldmatrix.sync.aligned.m8n8.x2.trans.shared.b16 {%0,%1}, [%2];"
        : "=r"(f[0]), "=r"(f[1]) : "r"(a));
}
__device__ __forceinline__ void mma16816(float c[4], const uint32_t a[4], const uint32_t b[2]) {
    asm volatile("mma.sync.aligned.m16n8k16.row.col.f32.bf16.bf16.f32 "
        "{%0,%1,%2,%3}, {%4,%5,%6,%7}, {%8,%9}, {%0,%1,%2,%3};"
        : "+f"(c[0]), "+f"(c[1]), "+f"(c[2]), "+f"(c[3])
        : "r"(a[0]), "r"(a[1]), "r"(a[2]), "r"(a[3]), "r"(b[0]), "r"(b[1]));
}

// ---------------- small kernels ----------------
// single CTA: zero counters, then stable-enough grouping (output is
// permutation-invariant per token, so atomic order doesn't matter)
__global__ void k_build(const int* __restrict__ xr) {
    if (threadIdx.x < RANKS) g_cnt[threadIdx.x] = 0;
    __syncthreads();
    for (int i = threadIdx.x; i < NT; i += 256) {
        int r = xr[i];
        int p = atomicAdd(&g_cnt[r], 1);
        g_list[r][p] = i;
    }
}

__global__ void k_prep_q(const float* __restrict__ q) {
    int i = blockIdx.x * 256 + threadIdx.x;              // 131072 groups of 8
    const float inv = 0.04419417382415922f;              // 1/sqrt(512)
    float4 a = *reinterpret_cast<const float4*>(q + (size_t)i * 8);
    float4 b = *reinterpret_cast<const float4*>(q + (size_t)i * 8 + 4);
    __nv_bfloat16 h[8];
    h[0] = __float2bfloat16(a.x * inv); h[1] = __float2bfloat16(a.y * inv);
    h[2] = __float2bfloat16(a.z * inv); h[3] = __float2bfloat16(a.w * inv);
    h[4] = __float2bfloat16(b.x * inv); h[5] = __float2bfloat16(b.y * inv);
    h[6] = __float2bfloat16(b.z * inv); h[7] = __float2bfloat16(b.w * inv);
    *reinterpret_cast<uint4*>(g_qh + (size_t)i * 8) = *reinterpret_cast<uint4*>(h);
}

__global__ void k_prep_emb(const float* __restrict__ emb) {
    int i = blockIdx.x * 256 + threadIdx.x;              // 2,097,152 groups of 8
    int d8 = i & 63;
    int vv = i >> 6;                                     // r*8192+v
    int r = vv >> 13, v = vv & 8191;
    __nv_bfloat16 h[8];
    if (v < SEG) {
        const float* s = emb + ((size_t)r * SEG + v) * DIM + d8 * 8;
        float4 a = *reinterpret_cast<const float4*>(s);
        float4 b = *reinterpret_cast<const float4*>(s + 4);
        h[0] = __float2bfloat16(a.x); h[1] = __float2bfloat16(a.y);
        h[2] = __float2bfloat16(a.z); h[3] = __float2bfloat16(a.w);
        h[4] = __float2bfloat16(b.x); h[5] = __float2bfloat16(b.y);
        h[6] = __float2bfloat16(b.z); h[7] = __float2bfloat16(b.w);
    } else {
        #pragma unroll
        for (int m = 0; m < 8; ++m) h[m] = __float2bfloat16(0.f);
    }
    *reinterpret_cast<uint4*>(g_embh + (size_t)vv * DIM + d8 * 8) = *reinterpret_cast<uint4*>(h);
}

// ---------------- pass 1: P = exp(Q.E^T), row-sum partials ----------------
// grid (16 token tiles, 4 ranks, 8 vsplits of 1024 rows); 256 thr; smem Q 128K + E 64K
__global__ void __launch_bounds__(256, 1)
k_scores() {
    int r = blockIdx.y;
    int cnt = g_cnt[r];
    int t0 = blockIdx.x * 128;
    if (t0 >= cnt) return;
    int vs = blockIdx.z;

    extern __shared__ char sm[];
    __shared__ int   toks[128];
    __shared__ float rs[2][128];

    const int tid = threadIdx.x, lane = tid & 31, wid = tid >> 5;
    const int mg = wid >> 1, ng = wid & 1;

    for (int i = tid; i < 128; i += 256) toks[i] = g_list[r][min(t0 + i, cnt - 1)];
    rs[tid >> 7][tid & 127] = 0.f;
    __syncthreads();

    const uint32_t qs = smem_u32(sm), es = qs + 131072;

    // Q tile: 128 rows x 64 chunks(16B), swizzled c^(row&7)
    for (int i = tid; i < 8192; i += 256) {
        int rr = i >> 6, c = i & 63;
        cpa16(qs + rr * 1024 + ((c ^ (rr & 7)) << 4),
              g_qh + (size_t)toks[rr] * DIM + c * 8);
    }
    CPA_COMMIT();

    // ldmatrix lane-constant pieces
    const int la7 = lane & 7;
    const int aRow0 = mg * 32 + la7 + ((lane >> 3) & 1) * 8;   // +mi*16
    const int aChB  = lane >> 4;                               // chunk add for A
    const int bRow0 = ng * 32 + la7;                           // +ni*8
    const int bChB  = (lane >> 3) & 1;
    const int epiV  = (lane & 3) * 2;

    const size_t vsbase = (size_t)vs * 1024;

    for (int tile = 0; tile < 16; ++tile) {
        __syncthreads();   // previous mma done reading Es
        // E tile: 64 rows x 64 chunks
        size_t v0 = vsbase + (size_t)tile * 64;
        const __nv_bfloat16* esrc = g_embh + ((size_t)r * SEGP + v0) * DIM;
        for (int i = tid; i < 4096; i += 256) {
            int rr = i >> 6, c = i & 63;
            cpa16(es + rr * 1024 + ((c ^ (rr & 7)) << 4),
                  esrc + (size_t)rr * DIM + c * 8);
        }
        CPA_COMMIT();
        CPA_WAIT(0);
        __syncthreads();

        float c[2][4][4];
        #pragma unroll
        for (int mi = 0; mi < 2; ++mi)
            #pragma unroll
            for (int ni = 0; ni < 4; ++ni)
                #pragma unroll
                for (int j = 0; j < 4; ++j) c[mi][ni][j] = 0.f;

        #pragma unroll 4
        for (int ks = 0; ks < 32; ++ks) {
            uint32_t a0[4], a1[4], b[2];
            uint32_t aswz = (uint32_t)(((ks * 2 + aChB) ^ la7) << 4);
            ldsm4(a0, qs + aRow0 * 1024 + aswz);
            ldsm4(a1, qs + (aRow0 + 16) * 1024 + aswz);
            uint32_t bswz = (uint32_t)(((ks * 2 + bChB) ^ la7) << 4);
            #pragma unroll
            for (int ni = 0; ni < 4; ++ni) {
                ldsm2(b, es + (bRow0 + ni * 8) * 1024 + bswz);
                mma16816(c[0][ni], a0, b);
                mma16816(c[1][ni], a1, b);
            }
        }

        // epilogue: exp, P->global (bf16), row sums
        int vb = (int)v0 + ng * 32;
        #pragma unroll
        for (int mi = 0; mi < 2; ++mi) {
            int rowlo = mg * 32 + mi * 16 + (lane >> 2);
            int rowhi = rowlo + 8;
            int toklo = toks[rowlo], tokhi = toks[rowhi];
            float slo = 0.f, shi = 0.f;
            #pragma unroll
            for (int ni = 0; ni < 4; ++ni) {
                int v = vb + ni * 8 + epiV;
                float p0 = (v     < SEG) ? __expf(c[mi][ni][0]) : 0.f;
                float p1 = (v + 1 < SEG) ? __expf(c[mi][ni][1]) : 0.f;
                float p2 = (v     < SEG) ? __expf(c[mi][ni][2]) : 0.f;
                float p3 = (v + 1 < SEG) ? __expf(c[mi][ni][3]) : 0.f;
                slo += p0 + p1; shi += p2 + p3;
                __nv_bfloat162 h0 = __floats2bfloat162_rn(p0, p1);
                __nv_bfloat162 h1 = __floats2bfloat162_rn(p2, p3);
                *reinterpret_cast<uint32_t*>(g_P + (size_t)toklo * SEGP + v) =
                    *reinterpret_cast<uint32_t*>(&h0);
                *reinterpret_cast<uint32_t*>(g_P + (size_t)tokhi * SEGP + v) =
                    *reinterpret_cast<uint32_t*>(&h1);
            }
            slo += __shfl_xor_sync(0xffffffffu, slo, 1);
            slo += __shfl_xor_sync(0xffffffffu, slo, 2);
            shi += __shfl_xor_sync(0xffffffffu, shi, 1);
            shi += __shfl_xor_sync(0xffffffffu, shi, 2);
            if ((lane & 3) == 0) { rs[ng][rowlo] += slo; rs[ng][rowhi] += shi; }
        }
    }
    __syncthreads();
    for (int i = tid; i < 128; i += 256)
        g_lpart[toks[i]][vs] = rs[0][i] + rs[1][i];
}

// ---------------- pass 2: out = (P.E)/l + q ----------------
// per chunk: P tile 128x64 (16KB) + E tile 64x64 (8KB), double-buffered
__device__ __forceinline__ void k2_load(uint32_t pt, uint32_t et, int buf,
                                        const int* toks, int rank, int ns,
                                        int ch, int tid) {
    size_t kc0 = (size_t)ch * 64;
    uint32_t pd = pt + buf * 16384, ed = et + buf * 8192;
    #pragma unroll
    for (int j = 0; j < 4; ++j) {                        // P: 128 rows x 8 chunks
        int i = tid + j * 256; int rr = i >> 3, cc = i & 7;
        cpa16(pd + rr * 128 + ((cc ^ (rr & 7)) << 4),
              g_P + (size_t)toks[rr] * SEGP + kc0 + cc * 8);
    }
    #pragma unroll
    for (int j = 0; j < 2; ++j) {                        // E: 64 rows x 8 chunks
        int i = tid + j * 256; int rr = i >> 3, cc = i & 7;
        cpa16(ed + rr * 128 + ((cc ^ (rr & 7)) << 4),
              g_embh + ((size_t)rank * SEGP + kc0 + rr) * DIM + (size_t)ns * 64 + cc * 8);
    }
}

// grid (16 token tiles, 4 ranks, 8 d-splits of 64); 256 thr; smem 48KB
__global__ void __launch_bounds__(256)
k_ctx(const float* __restrict__ qg, float* __restrict__ out) {
    int r = blockIdx.y;
    int cnt = g_cnt[r];
    int t0 = blockIdx.x * 128;
    if (t0 >= cnt) return;
    int ns = blockIdx.z;

    extern __shared__ char sm[];
    __shared__ int   toks[128];
    __shared__ float slinv[128];

    const int tid = threadIdx.x, lane = tid & 31, wid = tid >> 5;
    const int mg = wid >> 1, ng = wid & 1;

    for (int i = tid; i < 128; i += 256) toks[i] = g_list[r][min(t0 + i, cnt - 1)];
    __syncthreads();
    for (int i = tid; i < 128; i += 256) {
        int tok = toks[i];
        float l = 0.f;
        #pragma unroll
        for (int j = 0; j < 8; ++j) l += g_lpart[tok][j];
        slinv[i] = 1.f / l;
    }

    const uint32_t pt = smem_u32(sm), et = pt + 32768;

    float c[2][4][4];
    #pragma unroll
    for (int mi = 0; mi < 2; ++mi)
        #pragma unroll
        for (int ni = 0; ni < 4; ++ni)
            #pragma unroll
            for (int j = 0; j < 4; ++j) c[mi][ni][j] = 0.f;

    const int la7 = lane & 7;
    const int aRow0 = mg * 32 + la7 + ((lane >> 3) & 1) * 8;   // +mi*16
    const int aChB  = lane >> 4;
    const int bKr0  = la7 + ((lane >> 3) & 1) * 8;             // +ks*16

    k2_load(pt, et, 0, toks, r, ns, 0, tid);
    CPA_COMMIT();

    for (int ch = 0; ch < 128; ++ch) {
        if (ch < 127) {
            k2_load(pt, et, (ch + 1) & 1, toks, r, ns, ch + 1, tid);
            CPA_COMMIT();
            CPA_WAIT(1);
        } else {
            CPA_WAIT(0);
        }
        __syncthreads();

        uint32_t pb = pt + (ch & 1) * 16384;
        uint32_t eb = et + (ch & 1) * 8192;
        #pragma unroll
        for (int ks = 0; ks < 4; ++ks) {
            uint32_t a0[4], a1[4], b[2];
            uint32_t aswz = (uint32_t)(((ks * 2 + aChB) ^ la7) << 4);
            ldsm4(a0, pb + aRow0 * 128 + aswz);
            ldsm4(a1, pb + (aRow0 + 16) * 128 + aswz);
            int krow = ks * 16 + bKr0;
            #pragma unroll
            for (int ni = 0; ni < 4; ++ni) {
                ldsm2t(b, eb + krow * 128 + (((ng * 4 + ni) ^ la7) << 4));
                mma16816(c[0][ni], a0, b);
                mma16816(c[1][ni], a1, b);
            }
        }
        __syncthreads();
    }

    // epilogue: out = ctx*linv + q
    #pragma unroll
    for (int mi = 0; mi < 2; ++mi) {
        int rowlo = mg * 32 + mi * 16 + (lane >> 2);
        int rowhi = rowlo + 8;
        int toklo = toks[rowlo], tokhi = toks[rowhi];
        float ll = slinv[rowlo], lh = slinv[rowhi];
        #pragma unroll
        for (int ni = 0; ni < 4; ++ni) {
            int col = ns * 64 + ng * 32 + ni * 8 + (lane & 3) * 2;
            size_t olo = (size_t)toklo * DIM + col;
            size_t ohi = (size_t)tokhi * DIM + col;
            float2 qa = *reinterpret_cast<const float2*>(qg + olo);
            float2 qb = *reinterpret_cast<const float2*>(qg + ohi);
            float2 wa, wb;
            wa.x = c[mi][ni][0] * ll + qa.x; wa.y = c[mi][ni][1] * ll + qa.y;
            wb.x = c[mi][ni][2] * lh + qb.x; wb.y = c[mi][ni][3] * lh + qb.y;
            *reinterpret_cast<float2*>(out + olo) = wa;
            *reinterpret_cast<float2*>(out + ohi) = wb;
        }
    }
}

// ---------------- launch ----------------
extern "C" void kernel_launch(void* const* d_in, const int* in_sizes, int n_in,
                              void* d_out, int out_size) {
    const float* q   = (const float*)d_in[0];
    const int*   xr  = (const int*)  d_in[1];
    const float* emb = (const float*)d_in[2];
    float*       out = (float*)d_out;

    cudaFuncSetAttribute((const void*)k_scores,
                         cudaFuncAttributeMaxDynamicSharedMemorySize, 196608);
    cudaFuncSetAttribute((const void*)k_ctx,
                         cudaFuncAttributeMaxDynamicSharedMemorySize, 49152);

    k_build<<<1, 256>>>(xr);
    k_prep_q<<<512, 256>>>(q);
    k_prep_emb<<<8192, 256>>>(emb);

    dim3 g(16, 4, 8);
    k_scores<<<g, 256, 196608>>>();
    k_ctx<<<g, 256, 49152>>>(q, out);
}

// round 5
// speedup vs baseline: 8.2173x; 1.7157x over previous
#include <cuda_runtime.h>
#include <cuda_bf16.h>
#include <cstdint>

#define NT    2048
#define DIM   512
#define SEG   8000
#define SEGP  8192
#define RANKS 4
#define KSPL  8     // k-splits in pass 2 (K=1024 each)

// ---------------- scratch (device globals; no allocs allowed) ----------------
__device__ int g_cnt[RANKS];
__device__ int g_list[RANKS][NT];
__device__ __align__(128) __nv_bfloat16 g_qh[NT * DIM];                     // q*invT bf16
__device__ __align__(128) __nv_bfloat16 g_embh[(size_t)RANKS * SEGP * DIM]; // [r][v][d], padded
__device__ __align__(128) __nv_bfloat16 g_P[(size_t)NT * SEGP];             // exp(scores)
__device__ float g_lpart[NT][64];                                           // row-sum partials
__device__ float g_ctxp[KSPL][NT][DIM];                                     // ctx partials

// ---------------- helpers ----------------
__device__ __forceinline__ uint32_t smem_u32(const void* p) {
    uint32_t a;
    asm("{ .reg .u64 t; cvta.to.shared.u64 t, %1; cvt.u32.u64 %0, t; }" : "=r"(a) : "l"(p));
    return a;
}
__device__ __forceinline__ void cpa16(uint32_t d, const void* s) {
    asm volatile("cp.async.cg.shared.global [%0], [%1], 16;" :: "r"(d), "l"(s));
}
#define CPA_COMMIT() asm volatile("cp.async.commit_group;" ::: "memory")
#define CPA_WAIT(n)  asm volatile("cp.async.wait_group %0;" :: "n"(n) : "memory")

__device__ __forceinline__ void ldsm4(uint32_t f[4], uint32_t a) {
    asm volatile("ldmatrix.sync.aligned.m8n8.x4.shared.b16 {%0,%1,%2,%3}, [%4];"
        : "=r"(f[0]), "=r"(f[1]), "=r"(f[2]), "=r"(f[3]) : "r"(a));
}
__device__ __forceinline__ void ldsm2(uint32_t f[2], uint32_t a) {
    asm volatile("ldmatrix.sync.aligned.m8n8.x2.shared.b16 {%0,%1}, [%2];"
        : "=r"(f[0]), "=r"(f[1]) : "r"(a));
}
__device__ __forceinline__ void ldsm2t(uint32_t f[2], uint32_t a) {
    asm volatile("ldmatrix.sync.aligned.m8n8.x2.trans.shared.b16 {%0,%1}, [%2];"
        : "=r"(f[0]), "=r"(f[1]) : "r"(a));
}
__device__ __forceinline__ void mma16816(float c[4], const uint32_t a[4], const uint32_t b[2]) {
    asm volatile("mma.sync.aligned.m16n8k16.row.col.f32.bf16.bf16.f32 "
        "{%0,%1,%2,%3}, {%4,%5,%6,%7}, {%8,%9}, {%0,%1,%2,%3};"
        : "+f"(c[0]), "+f"(c[1]), "+f"(c[2]), "+f"(c[3])
        : "r"(a[0]), "r"(a[1]), "r"(a[2]), "r"(a[3]), "r"(b[0]), "r"(b[1]));
}

// ---------------- small kernels ----------------
__global__ void k_build(const int* __restrict__ xr) {
    if (threadIdx.x < RANKS) g_cnt[threadIdx.x] = 0;
    __syncthreads();
    for (int i = threadIdx.x; i < NT; i += 256) {
        int r = xr[i];
        int p = atomicAdd(&g_cnt[r], 1);
        g_list[r][p] = i;
    }
}

__global__ void k_prep_q(const float* __restrict__ q) {
    int i = blockIdx.x * 256 + threadIdx.x;
    const float inv = 0.04419417382415922f;   // 1/sqrt(512)
    float4 a = *reinterpret_cast<const float4*>(q + (size_t)i * 8);
    float4 b = *reinterpret_cast<const float4*>(q + (size_t)i * 8 + 4);
    __nv_bfloat16 h[8];
    h[0] = __float2bfloat16(a.x * inv); h[1] = __float2bfloat16(a.y * inv);
    h[2] = __float2bfloat16(a.z * inv); h[3] = __float2bfloat16(a.w * inv);
    h[4] = __float2bfloat16(b.x * inv); h[5] = __float2bfloat16(b.y * inv);
    h[6] = __float2bfloat16(b.z * inv); h[7] = __float2bfloat16(b.w * inv);
    *reinterpret_cast<uint4*>(g_qh + (size_t)i * 8) = *reinterpret_cast<uint4*>(h);
}

__global__ void k_prep_emb(const float* __restrict__ emb) {
    int i = blockIdx.x * 256 + threadIdx.x;
    int d8 = i & 63;
    int vv = i >> 6;
    int r = vv >> 13, v = vv & 8191;
    __nv_bfloat16 h[8];
    if (v < SEG) {
        const float* s = emb + ((size_t)r * SEG + v) * DIM + d8 * 8;
        float4 a = *reinterpret_cast<const float4*>(s);
        float4 b = *reinterpret_cast<const float4*>(s + 4);
        h[0] = __float2bfloat16(a.x); h[1] = __float2bfloat16(a.y);
        h[2] = __float2bfloat16(a.z); h[3] = __float2bfloat16(a.w);
        h[4] = __float2bfloat16(b.x); h[5] = __float2bfloat16(b.y);
        h[6] = __float2bfloat16(b.z); h[7] = __float2bfloat16(b.w);
    } else {
        #pragma unroll
        for (int m = 0; m < 8; ++m) h[m] = __float2bfloat16(0.f);
    }
    *reinterpret_cast<uint4*>(g_embh + (size_t)vv * DIM + d8 * 8) = *reinterpret_cast<uint4*>(h);
}

// ---------------- pass 1: P = exp(Q.E^T), row-sum partials ----------------
// C tile 128 tok x 128 vocab, K=512 in 8 chunks of 64, double-buffered.
// grid (16 token tiles, 4 ranks, 64 vsplits); 256 thr; smem 64KB
__device__ __forceinline__ void k1_load(uint32_t smb, int buf, const int* toks,
                                        const __nv_bfloat16* esrc, int kc0, int tid) {
    uint32_t pd = smb + buf * 32768, ed = pd + 16384;
    #pragma unroll
    for (int j = 0; j < 4; ++j) {                       // A=Q: 128 rows x 8 chunks
        int i = tid + j * 256; int rr = i >> 3, cc = i & 7;
        cpa16(pd + rr * 128 + ((cc ^ (rr & 7)) << 4),
              g_qh + (size_t)toks[rr] * DIM + kc0 + cc * 8);
    }
    #pragma unroll
    for (int j = 0; j < 4; ++j) {                       // B=E: 128 rows x 8 chunks
        int i = tid + j * 256; int rr = i >> 3, cc = i & 7;
        cpa16(ed + rr * 128 + ((cc ^ (rr & 7)) << 4),
              esrc + (size_t)rr * DIM + kc0 + cc * 8);
    }
}

__global__ void __launch_bounds__(256)
k_scores() {
    int r = blockIdx.y;
    int cnt = g_cnt[r];
    int t0 = blockIdx.x * 128;
    if (t0 >= cnt) return;
    int vs = blockIdx.z;

    extern __shared__ char sm[];
    __shared__ int   toks[128];
    __shared__ float rs[2][128];

    const int tid = threadIdx.x, lane = tid & 31, wid = tid >> 5;
    const int mg = wid >> 1, ng = wid & 1;

    for (int i = tid; i < 128; i += 256) toks[i] = g_list[r][min(t0 + i, cnt - 1)];
    __syncthreads();

    const uint32_t smb = smem_u32(sm);
    const __nv_bfloat16* esrc = g_embh + ((size_t)r * SEGP + (size_t)vs * 128) * DIM;

    const int la7 = lane & 7;
    const int aRow0 = mg * 32 + la7 + ((lane >> 3) & 1) * 8;
    const int aChB  = lane >> 4;
    const int bRow0 = ng * 64 + la7;
    const int bChB  = (lane >> 3) & 1;
    const int epiV  = (lane & 3) * 2;

    float c[2][8][4];
    #pragma unroll
    for (int mi = 0; mi < 2; ++mi)
        #pragma unroll
        for (int ni = 0; ni < 8; ++ni)
            #pragma unroll
            for (int j = 0; j < 4; ++j) c[mi][ni][j] = 0.f;

    k1_load(smb, 0, toks, esrc, 0, tid);
    CPA_COMMIT();

    for (int ch = 0; ch < 8; ++ch) {
        if (ch < 7) {
            k1_load(smb, (ch + 1) & 1, toks, esrc, (ch + 1) * 64, tid);
            CPA_COMMIT();
            CPA_WAIT(1);
        } else {
            CPA_WAIT(0);
        }
        __syncthreads();

        uint32_t pb = smb + (ch & 1) * 32768;
        uint32_t eb = pb + 16384;
        #pragma unroll
        for (int ks = 0; ks < 4; ++ks) {
            uint32_t a0[4], a1[4], b[2];
            uint32_t aswz = (uint32_t)(((ks * 2 + aChB) ^ la7) << 4);
            ldsm4(a0, pb + aRow0 * 128 + aswz);
            ldsm4(a1, pb + (aRow0 + 16) * 128 + aswz);
            uint32_t bswz = (uint32_t)(((ks * 2 + bChB) ^ la7) << 4);
            #pragma unroll
            for (int ni = 0; ni < 8; ++ni) {
                ldsm2(b, eb + (bRow0 + ni * 8) * 128 + bswz);
                mma16816(c[0][ni], a0, b);
                mma16816(c[1][ni], a1, b);
            }
        }
        __syncthreads();
    }

    // epilogue: exp, P->global (bf16), row sums (once per CTA)
    #pragma unroll
    for (int mi = 0; mi < 2; ++mi) {
        int rowlo = mg * 32 + mi * 16 + (lane >> 2);
        int rowhi = rowlo + 8;
        int toklo = toks[rowlo], tokhi = toks[rowhi];
        float slo = 0.f, shi = 0.f;
        #pragma unroll
        for (int ni = 0; ni < 8; ++ni) {
            int v = vs * 128 + ng * 64 + ni * 8 + epiV;
            float p0 = (v     < SEG) ? __expf(c[mi][ni][0]) : 0.f;
            float p1 = (v + 1 < SEG) ? __expf(c[mi][ni][1]) : 0.f;
            float p2 = (v     < SEG) ? __expf(c[mi][ni][2]) : 0.f;
            float p3 = (v + 1 < SEG) ? __expf(c[mi][ni][3]) : 0.f;
            slo += p0 + p1; shi += p2 + p3;
            __nv_bfloat162 h0 = __floats2bfloat162_rn(p0, p1);
            __nv_bfloat162 h1 = __floats2bfloat162_rn(p2, p3);
            *reinterpret_cast<uint32_t*>(g_P + (size_t)toklo * SEGP + v) =
                *reinterpret_cast<uint32_t*>(&h0);
            *reinterpret_cast<uint32_t*>(g_P + (size_t)tokhi * SEGP + v) =
                *reinterpret_cast<uint32_t*>(&h1);
        }
        slo += __shfl_xor_sync(0xffffffffu, slo, 1);
        slo += __shfl_xor_sync(0xffffffffu, slo, 2);
        shi += __shfl_xor_sync(0xffffffffu, shi, 1);
        shi += __shfl_xor_sync(0xffffffffu, shi, 2);
        if ((lane & 3) == 0) { rs[ng][rowlo] = slo; rs[ng][rowhi] = shi; }
    }
    __syncthreads();
    for (int i = tid; i < 128; i += 256)
        g_lpart[toks[i]][vs] = rs[0][i] + rs[1][i];
}

// ---------------- pass 2: ctx partials = P.E over a K slice ----------------
// C tile 128 tok x 128 dim, K=1024 per CTA in 16 chunks of 64, double-buffered.
// grid (16 tiles, 4 ranks, 8 ksplits * 4 dsplits); 256 thr; smem 64KB
__device__ __forceinline__ void k2_load(uint32_t smb, int buf, const int* toks,
                                        int rank, int ns, int kc0, int tid) {
    uint32_t pd = smb + buf * 32768, ed = pd + 16384;
    #pragma unroll
    for (int j = 0; j < 4; ++j) {                       // A=P: 128 rows x 8 chunks
        int i = tid + j * 256; int rr = i >> 3, cc = i & 7;
        cpa16(pd + rr * 128 + ((cc ^ (rr & 7)) << 4),
              g_P + (size_t)toks[rr] * SEGP + kc0 + cc * 8);
    }
    #pragma unroll
    for (int j = 0; j < 4; ++j) {                       // B=E: 64 rows x 16 chunks
        int i = tid + j * 256; int rr = i >> 4, cc = i & 15;
        cpa16(ed + rr * 256 + ((cc ^ (rr & 7)) << 4),
              g_embh + ((size_t)rank * SEGP + kc0 + rr) * DIM + (size_t)ns * 128 + cc * 8);
    }
}

__global__ void __launch_bounds__(256)
k_ctx() {
    int r = blockIdx.y;
    int cnt = g_cnt[r];
    int t0 = blockIdx.x * 128;
    if (t0 >= cnt) return;
    int kz = blockIdx.z >> 2;       // 0..7
    int ns = blockIdx.z & 3;        // 0..3

    extern __shared__ char sm[];
    __shared__ int toks[128];

    const int tid = threadIdx.x, lane = tid & 31, wid = tid >> 5;
    const int mg = wid >> 1, ng = wid & 1;

    for (int i = tid; i < 128; i += 256) toks[i] = g_list[r][min(t0 + i, cnt - 1)];
    __syncthreads();

    const uint32_t smb = smem_u32(sm);

    const int la7 = lane & 7;
    const int aRow0 = mg * 32 + la7 + ((lane >> 3) & 1) * 8;
    const int aChB  = lane >> 4;
    const int bKr0  = la7 + ((lane >> 3) & 1) * 8;

    float c[2][8][4];
    #pragma unroll
    for (int mi = 0; mi < 2; ++mi)
        #pragma unroll
        for (int ni = 0; ni < 8; ++ni)
            #pragma unroll
            for (int j = 0; j < 4; ++j) c[mi][ni][j] = 0.f;

    const int kbase = kz * 1024;
    k2_load(smb, 0, toks, r, ns, kbase, tid);
    CPA_COMMIT();

    for (int ch = 0; ch < 16; ++ch) {
        if (ch < 15) {
            k2_load(smb, (ch + 1) & 1, toks, r, ns, kbase + (ch + 1) * 64, tid);
            CPA_COMMIT();
            CPA_WAIT(1);
        } else {
            CPA_WAIT(0);
        }
        __syncthreads();

        uint32_t pb = smb + (ch & 1) * 32768;
        uint32_t eb = pb + 16384;
        #pragma unroll
        for (int ks = 0; ks < 4; ++ks) {
            uint32_t a0[4], a1[4], b[2];
            uint32_t aswz = (uint32_t)(((ks * 2 + aChB) ^ la7) << 4);
            ldsm4(a0, pb + aRow0 * 128 + aswz);
            ldsm4(a1, pb + (aRow0 + 16) * 128 + aswz);
            int krow = ks * 16 + bKr0;
            #pragma unroll
            for (int ni = 0; ni < 8; ++ni) {
                ldsm2t(b, eb + krow * 256 + (((ng * 8 + ni) ^ la7) << 4));
                mma16816(c[0][ni], a0, b);
                mma16816(c[1][ni], a1, b);
            }
        }
        __syncthreads();
    }

    // epilogue: raw partials to g_ctxp[kz]
    #pragma unroll
    for (int mi = 0; mi < 2; ++mi) {
        int rowlo = mg * 32 + mi * 16 + (lane >> 2);
        int rowhi = rowlo + 8;
        int toklo = toks[rowlo], tokhi = toks[rowhi];
        #pragma unroll
        for (int ni = 0; ni < 8; ++ni) {
            int col = ns * 128 + ng * 64 + ni * 8 + (lane & 3) * 2;
            float2 wa, wb;
            wa.x = c[mi][ni][0]; wa.y = c[mi][ni][1];
            wb.x = c[mi][ni][2]; wb.y = c[mi][ni][3];
            *reinterpret_cast<float2*>(&g_ctxp[kz][toklo][col]) = wa;
            *reinterpret_cast<float2*>(&g_ctxp[kz][tokhi][col]) = wb;
        }
    }
}

// ---------------- final: out = (sum_ks ctxp)/l + q ----------------
__global__ void k_final(const float* __restrict__ qg, float* __restrict__ out) {
    int tok = blockIdx.x;
    int lane = threadIdx.x;   // 32
    float l = g_lpart[tok][lane] + g_lpart[tok][lane + 32];
    #pragma unroll
    for (int o = 16; o; o >>= 1) l += __shfl_xor_sync(0xffffffffu, l, o);
    float linv = 1.f / l;
    #pragma unroll
    for (int j = 0; j < 4; ++j) {
        int d = (j * 32 + lane) * 4;
        float4 s = *reinterpret_cast<const float4*>(&g_ctxp[0][tok][d]);
        #pragma unroll
        for (int k = 1; k < KSPL; ++k) {
            float4 t = *reinterpret_cast<const float4*>(&g_ctxp[k][tok][d]);
            s.x += t.x; s.y += t.y; s.z += t.z; s.w += t.w;
        }
        float4 qv = *reinterpret_cast<const float4*>(qg + (size_t)tok * DIM + d);
        float4 o4;
        o4.x = s.x * linv + qv.x; o4.y = s.y * linv + qv.y;
        o4.z = s.z * linv + qv.z; o4.w = s.w * linv + qv.w;
        *reinterpret_cast<float4*>(out + (size_t)tok * DIM + d) = o4;
    }
}

// ---------------- launch ----------------
extern "C" void kernel_launch(void* const* d_in, const int* in_sizes, int n_in,
                              void* d_out, int out_size) {
    const float* q   = (const float*)d_in[0];
    const int*   xr  = (const int*)  d_in[1];
    const float* emb = (const float*)d_in[2];
    float*       out = (float*)d_out;

    cudaFuncSetAttribute((const void*)k_scores,
                         cudaFuncAttributeMaxDynamicSharedMemorySize, 65536);
    cudaFuncSetAttribute((const void*)k_ctx,
                         cudaFuncAttributeMaxDynamicSharedMemorySize, 65536);

    k_build<<<1, 256>>>(xr);
    k_prep_q<<<512, 256>>>(q);
    k_prep_emb<<<8192, 256>>>(emb);

    dim3 g1(16, 4, 64);
    k_scores<<<g1, 256, 65536>>>();
    dim3 g2(16, 4, 32);
    k_ctx<<<g2, 256, 65536>>>();
    k_final<<<NT, 32>>>(q, out);
}